// round 5
// baseline (speedup 1.0000x reference)
#include <cuda_runtime.h>
#include <math.h>
#include <stdint.h>

// ---------------------------------------------------------------------------
// DDDDepthDiff R5: 4-node graph; selection fused into k3 tail, final into k5
// ---------------------------------------------------------------------------

#define HW       230400       // 360*640
#define WIDTH    640
#define NPLANES  1000
#define MINPTS   5000
#define SPAN     230400u

#define PIX_BLOCKS (HW / 256)        // 900
#define K3_CHUNK   512
#define K3_BLOCKS  (HW / K3_CHUNK)   // 450
#define K3_THREADS 256
#define PPT        4                 // planes per thread (256*4 = 1024)

typedef unsigned long long u64;

// ----------------------------- scratch ------------------------------------
__device__ float g_cx[HW];
__device__ float g_cy[HW];
__device__ float g_cz[HW];
__device__ float4 g_planes[NPLANES];
__device__ unsigned g_counts[NPLANES];   // zero-init; k3 tail re-zeros
__device__ unsigned g_tick3, g_tick5;    // zero-init; tails reset

#define ENC_NEG_INF 0x007FFFFFu
#define ENC_POS_INF 0xFF800000u

struct Accum {
    double sumX, sumY, sumZ, sumLog;
    unsigned long long cntM;
    int gmaxBits;
    unsigned zmaxEnc, zminEnc;
    unsigned long long icnt;
    double sumZc;
    float4 bestPlane;
    float R20, R21, R22, dz, thresh;
};
__device__ Accum g_acc = { 0.0, 0.0, 0.0, 0.0, 0ull, 0,
                           ENC_NEG_INF, ENC_POS_INF, 0ull, 0.0,
                           {0.f,0.f,0.f,0.f}, 0.f,0.f,0.f,0.f,0.f };

// ----------------------------- helpers ------------------------------------
__device__ __forceinline__ unsigned encf(float f) {
    unsigned u = __float_as_uint(f);
    return (u & 0x80000000u) ? ~u : (u | 0x80000000u);
}
__device__ __forceinline__ float decf(unsigned e) {
    return (e & 0x80000000u) ? __uint_as_float(e ^ 0x80000000u) : __uint_as_float(~e);
}

__device__ __forceinline__ float wred_add_f(float v) {
    #pragma unroll
    for (int o = 16; o; o >>= 1) v += __shfl_down_sync(0xffffffffu, v, o);
    return v;
}
__device__ __forceinline__ int wred_add_i(int v) {
    #pragma unroll
    for (int o = 16; o; o >>= 1) v += __shfl_down_sync(0xffffffffu, v, o);
    return v;
}
__device__ __forceinline__ float wred_max_f(float v) {
    #pragma unroll
    for (int o = 16; o; o >>= 1) v = fmaxf(v, __shfl_down_sync(0xffffffffu, v, o));
    return v;
}
__device__ __forceinline__ float wred_min_f(float v) {
    #pragma unroll
    for (int o = 16; o; o >>= 1) v = fminf(v, __shfl_down_sync(0xffffffffu, v, o));
    return v;
}
__device__ __forceinline__ int wred_max_i(int v) {
    #pragma unroll
    for (int o = 16; o; o >>= 1) v = max(v, __shfl_down_sync(0xffffffffu, v, o));
    return v;
}

// packed f32x2 ops (sm_103a FFMA2 path — only reachable via PTX)
__device__ __forceinline__ u64 pack2(float lo, float hi) {
    u64 r; asm("mov.b64 %0, {%1, %2};" : "=l"(r) : "f"(lo), "f"(hi)); return r;
}
__device__ __forceinline__ u64 fma2(u64 a, u64 b, u64 c) {
    u64 d; asm("fma.rn.f32x2 %0, %1, %2, %3;" : "=l"(d) : "l"(a), "l"(b), "l"(c)); return d;
}
__device__ __forceinline__ void unpack2(u64 v, unsigned& lo, unsigned& hi) {
    asm("mov.b64 {%0, %1}, %2;" : "=r"(lo), "=r"(hi) : "l"(v));
}

// ---- threefry-2x32 (JAX partitionable mode), keys folded at compile time ---
struct TFOut { unsigned x0, x1; };
constexpr unsigned rotl32(unsigned x, unsigned r) { return (x << r) | (x >> (32u - r)); }
constexpr TFOut tf_const(unsigned k0, unsigned k1, unsigned x0, unsigned x1) {
    unsigned ks0 = k0, ks1 = k1, ks2 = 0x1BD11BDAu ^ k0 ^ k1;
    const unsigned rA[4] = { 13u, 15u, 26u, 6u };
    const unsigned rB[4] = { 17u, 29u, 16u, 24u };
    x0 += ks0; x1 += ks1;
    for (int i = 0; i < 5; ++i) {
        for (int j = 0; j < 4; ++j) {
            unsigned r = ((i & 1) == 0) ? rA[j] : rB[j];
            x0 += x1; x1 = rotl32(x1, r); x1 ^= x0;
        }
        const unsigned kss[3] = { ks0, ks1, ks2 };
        x0 += kss[(i + 1) % 3];
        x1 += kss[(i + 2) % 3] + (unsigned)(i + 1);
    }
    return { x0, x1 };
}
// key(42)->(0,42); split -> k2 = tf(0,1). randint's multiplier wraps to 0 in
// uint32 (65536^2 mod 2^32 == 0), so idx = lower_bits(k2, i) % SPAN only.
constexpr TFOut KB = tf_const(0u, 42u, 0u, 1u);

__device__ __forceinline__ unsigned tf_bits_lo(unsigned ctr) {
    unsigned x0 = 0u, x1 = ctr;
    unsigned ks[3] = { KB.x0, KB.x1, 0x1BD11BDAu ^ KB.x0 ^ KB.x1 };
    const unsigned rA[4] = { 13u, 15u, 26u, 6u };
    const unsigned rB[4] = { 17u, 29u, 16u, 24u };
    x0 += ks[0]; x1 += ks[1];
    #pragma unroll
    for (int i = 0; i < 5; ++i) {
        #pragma unroll
        for (int j = 0; j < 4; ++j) {
            unsigned r = ((i & 1) == 0) ? rA[j] : rB[j];
            x0 += x1;
            x1 = (x1 << r) | (x1 >> (32u - r));
            x1 ^= x0;
        }
        x0 += ks[(i + 1) % 3];
        x1 += ks[(i + 2) % 3] + (unsigned)(i + 1);
    }
    return x0 ^ x1;
}

// Scalar inlier predicate for k5 — same rounding as the packed path's d.
__device__ __forceinline__ float plane_dist(float4 pl, float px, float py, float pz) {
    return __fmaf_rn(pl.x, px, __fmaf_rn(pl.y, py, __fmaf_rn(pl.z, pz, pl.w)));
}

// ----------------------------- kernel 1 ------------------------------------
// Per-pixel losses + fake cloud. 1 pixel/thread, float block partials,
// double atomics once per block.
__global__ __launch_bounds__(256)
void k1_stats(const float* __restrict__ fake, const float* __restrict__ real) {
    int i = blockIdx.x * 256 + threadIdx.x;   // PIX_BLOCKS*256 == HW
    int r = i / WIDTH;
    int col = i - r * WIDTH;
    float cc = (float)col - 334.081f;
    float rr = (float)r - 169.808f;
    float dr = real[i], df = fake[i];
    bool vr = (dr > 0.0f) && (dr < 65535.0f);
    bool vf = (df > 0.0f) && (df < 65535.0f);

    // fake cloud: EXACT divisions (feeds gmax -> plane selection; keep bitwise)
    float fz = df / 1000.0f;
    float fxp = (fz * cc) / 460.585f;
    float fyp = (fz * rr) / 460.268f;
    float FXv = fxp * 1000.0f, FYv = fyp * 1000.0f, FZv = fz * 1000.0f;
    if (FXv == 0.0f) FXv = 1e-7f;
    if (FYv == 0.0f) FYv = 1e-7f;
    if (FZv == 0.0f) FZv = 1e-7f;
    float ox = vf ? FXv : 0.0f;
    float oy = vf ? FYv : 0.0f;
    float oz = vf ? FZv : 0.0f;
    g_cx[i] = ox; g_cy[i] = oy; g_cz[i] = oz;
    float mx = fmaxf(0.0f, fmaxf(ox, fmaxf(oy, oz)));

    float sX = 0.f, sY = 0.f, sZ = 0.f, sL = 0.f;
    int c = 0;
    if (vr && vf) {
        float rz = dr * (1.0f / 1000.0f);
        float rxp = (rz * cc) * (1.0f / 460.585f);
        float ryp = (rz * rr) * (1.0f / 460.268f);
        float RXv = rxp * 1000.0f, RYv = ryp * 1000.0f, RZv = rz * 1000.0f;
        if (RXv == 0.0f) RXv = 1e-7f;
        if (RYv == 0.0f) RYv = 1e-7f;
        if (RZv == 0.0f) RZv = 1e-7f;
        float dx = RXv - FXv, dy = RYv - FYv, dz = RZv - FZv;
        sX = dx * dx; sY = dy * dy; sZ = dz * dz;
        float dl = __logf(fabsf(RZv)) - __logf(fabsf(FZv));
        sL = dl * dl;
        c = 1;
    }

    sX = wred_add_f(sX); sY = wred_add_f(sY); sZ = wred_add_f(sZ); sL = wred_add_f(sL);
    c = wred_add_i(c);
    mx = wred_max_f(mx);

    __shared__ float rs[8][6];
    int wid = threadIdx.x >> 5;
    if ((threadIdx.x & 31) == 0) {
        rs[wid][0] = sX; rs[wid][1] = sY; rs[wid][2] = sZ;
        rs[wid][3] = sL; rs[wid][4] = (float)c; rs[wid][5] = mx;
    }
    __syncthreads();
    if (threadIdx.x == 0) {
        float tX = 0.f, tY = 0.f, tZ = 0.f, tL = 0.f, tC = 0.f, tM = 0.f;
        #pragma unroll
        for (int w = 0; w < 8; ++w) {
            tX += rs[w][0]; tY += rs[w][1]; tZ += rs[w][2];
            tL += rs[w][3]; tC += rs[w][4]; tM = fmaxf(tM, rs[w][5]);
        }
        atomicAdd(&g_acc.sumX, (double)tX);
        atomicAdd(&g_acc.sumY, (double)tY);
        atomicAdd(&g_acc.sumZ, (double)tZ);
        atomicAdd(&g_acc.sumLog, (double)tL);
        atomicAdd(&g_acc.cntM, (unsigned long long)(int)tC);
        atomicMax(&g_acc.gmaxBits, __float_as_int(tM));   // tM >= 0
    }
}

// ----------------------------- kernel 2 ------------------------------------
// Threshold + 1000 plane hypotheses.
__global__ __launch_bounds__(256)
void k2_planes(const int* __restrict__ epoch_ptr) {
    int t = blockIdx.x * 256 + threadIdx.x;
    if (t == 0) {
        int epoch = epoch_ptr[0];
        float thf = (float)(0.025 - 0.001 * (double)epoch);
        g_acc.thresh = fmaxf(thf, 0.005f);
    }
    if (t >= NPLANES) return;

    int ids[3];
    #pragma unroll
    for (int j = 0; j < 3; ++j)
        ids[j] = (int)(tf_bits_lo((unsigned)(t * 3 + j)) % SPAN);

    float gmax = __int_as_float(g_acc.gmaxBits);
    float p0x = g_cx[ids[0]] / gmax, p0y = g_cy[ids[0]] / gmax, p0z = g_cz[ids[0]] / gmax;
    float p1x = g_cx[ids[1]] / gmax, p1y = g_cy[ids[1]] / gmax, p1z = g_cz[ids[1]] / gmax;
    float p2x = g_cx[ids[2]] / gmax, p2y = g_cy[ids[2]] / gmax, p2z = g_cz[ids[2]] / gmax;

    float ax = p1x - p0x, ay = p1y - p0y, az = p1z - p0z;
    float bx = p2x - p0x, by = p2y - p0y, bz = p2z - p0z;
    float nx = ay * bz - az * by;
    float ny = az * bx - ax * bz;
    float nz = ax * by - ay * bx;
    float nn = sqrtf(nx * nx + ny * ny + nz * nz);
    nx /= nn; ny /= nn; nz /= nn;
    float kk = -(nx * p1x + ny * p1y + nz * p1z);
    g_planes[t] = make_float4(nx, ny, nz, kk);
}

// ----------------------------- kernel 3 ------------------------------------
// Packed f32x2 inlier counting (PPT=4); tail: selection + rotation + reset.
__global__ __launch_bounds__(K3_THREADS)
void k3_count() {
    __shared__ __align__(16) u64 sx2[K3_CHUNK / 2];
    __shared__ __align__(16) u64 sy2[K3_CHUNK / 2];
    __shared__ __align__(16) u64 sz2[K3_CHUNK / 2];

    int base = blockIdx.x * K3_CHUNK;
    float gmax = __int_as_float(g_acc.gmaxBits);
    float th = g_acc.thresh;
    u64 NEGTH2 = pack2(-th * th, -th * th);

    {
        int j = threadIdx.x;           // K3_CHUNK/2 == K3_THREADS
        float2 vx = ((const float2*)(g_cx + base))[j];
        float2 vy = ((const float2*)(g_cy + base))[j];
        float2 vz = ((const float2*)(g_cz + base))[j];
        ((float2*)sx2)[j] = make_float2(vx.x / gmax, vx.y / gmax);
        ((float2*)sy2)[j] = make_float2(vy.x / gmax, vy.y / gmax);
        ((float2*)sz2)[j] = make_float2(vz.x / gmax, vz.y / gmax);
    }

    u64 PX[PPT], PY[PPT], PZ[PPT], PW[PPT];
    unsigned cnt[PPT];
    int pid[PPT];
    #pragma unroll
    for (int k = 0; k < PPT; ++k) {
        pid[k] = threadIdx.x + k * K3_THREADS;
        float4 pl = (pid[k] < NPLANES) ? g_planes[pid[k]]
                                       : make_float4(0.0f, 0.0f, 0.0f, 1e18f);
        PX[k] = pack2(pl.x, pl.x);
        PY[k] = pack2(pl.y, pl.y);
        PZ[k] = pack2(pl.z, pl.z);
        PW[k] = pack2(pl.w, pl.w);
        cnt[k] = 0u;
    }
    __syncthreads();

    const ulonglong2* sxv = (const ulonglong2*)sx2;   // 128 entries
    const ulonglong2* syv = (const ulonglong2*)sy2;
    const ulonglong2* szv = (const ulonglong2*)sz2;

    #pragma unroll 4
    for (int jj = 0; jj < K3_CHUNK / 4; ++jj) {
        ulonglong2 X2 = sxv[jj];                       // LDS.128 broadcast
        ulonglong2 Y2 = syv[jj];
        ulonglong2 Z2 = szv[jj];
        #pragma unroll
        for (int k = 0; k < PPT; ++k) {
            u64 d0 = fma2(PX[k], X2.x, fma2(PY[k], Y2.x, fma2(PZ[k], Z2.x, PW[k])));
            u64 u0 = fma2(d0, d0, NEGTH2);
            unsigned lo0, hi0; unpack2(u0, lo0, hi0);
            cnt[k] += (lo0 >> 31) + (hi0 >> 31);
            u64 d1 = fma2(PX[k], X2.y, fma2(PY[k], Y2.y, fma2(PZ[k], Z2.y, PW[k])));
            u64 u1 = fma2(d1, d1, NEGTH2);
            unsigned lo1, hi1; unpack2(u1, lo1, hi1);
            cnt[k] += (lo1 >> 31) + (hi1 >> 31);
        }
    }

    #pragma unroll
    for (int k = 0; k < PPT; ++k)
        if (pid[k] < NPLANES) atomicAdd(&g_counts[pid[k]], cnt[k]);

    // ---- last-block tail: best-plane selection + rotation + counts reset ----
    __shared__ unsigned s_last;
    __syncthreads();
    if (threadIdx.x == 0) {
        __threadfence();
        s_last = atomicAdd(&g_tick3, 1u);
    }
    __syncthreads();
    if (s_last != gridDim.x - 1) return;
    __threadfence();

    int best_key = -1;
    #pragma unroll
    for (int k = 0; k < PPT; ++k) {
        int t = threadIdx.x + k * K3_THREADS;
        if (t < NPLANES) {
            int cc = (int)__ldcg(&g_counts[t]);
            int score = (cc > MINPTS) ? cc : -1;
            best_key = max(best_key, ((score + 1) << 12) | (1023 - t));
        }
    }
    best_key = wred_max_i(best_key);
    __shared__ int skey[8];
    int wid = threadIdx.x >> 5;
    if ((threadIdx.x & 31) == 0) skey[wid] = best_key;
    __syncthreads();
    #pragma unroll
    for (int k = 0; k < PPT; ++k) {
        int t = threadIdx.x + k * K3_THREADS;
        if (t < NPLANES) g_counts[t] = 0u;            // reset for next replay
    }
    if (threadIdx.x == 0) {
        int mk = skey[0];
        #pragma unroll
        for (int w = 1; w < 8; ++w) mk = max(mk, skey[w]);
        int best = 1023 - (mk & 0xFFF);
        float4 bp = g_planes[best];
        g_acc.bestPlane = bp;
        float a = bp.x, b = bp.y, c = bp.z, d = bp.w;
        float n2 = a * a + b * b + c * c;
        float cos_t = c / sqrtf(n2);
        float sin_t = sqrtf((a * a + b * b) / n2);
        float sab = sqrtf(a * a + b * b);
        float u1 = b / sab;
        float u2 = -a / sab;
        g_acc.dz = d / c;
        g_acc.R20 = -u2 * sin_t;
        g_acc.R21 = u1 * sin_t;
        g_acc.R22 = cos_t;
        g_tick3 = 0u;
    }
}

// ----------------------------- kernel 5 ------------------------------------
// Inlier z stats; tail: finalize outputs + reset accumulators for replay.
__global__ __launch_bounds__(256)
void k5_stats(float* __restrict__ out, int out_size) {
    int i = blockIdx.x * 256 + threadIdx.x;
    float gmax = __int_as_float(g_acc.gmaxBits);
    float th = g_acc.thresh;
    float4 bp = g_acc.bestPlane;
    float R20 = g_acc.R20, R21 = g_acc.R21, R22 = g_acc.R22, dz = g_acc.dz;
    const float INF = __int_as_float(0x7f800000);

    float px = g_cx[i] / gmax, py = g_cy[i] / gmax, pz = g_cz[i] / gmax;
    float d = plane_dist(bp, px, py, pz);
    bool in = (fabsf(d) <= th);
    float zc = __fmaf_rn(pz + dz, R22, __fmaf_rn(py, R21, px * R20));
    float zmx = in ? zc : -INF;
    float zmn = in ? zc : INF;
    float sZc = in ? zc : 0.0f;
    int ic = in ? 1 : 0;

    zmx = wred_max_f(zmx);
    zmn = wred_min_f(zmn);
    sZc = wred_add_f(sZc);
    ic = wred_add_i(ic);

    __shared__ float rs[8][4];
    int wid = threadIdx.x >> 5;
    if ((threadIdx.x & 31) == 0) {
        rs[wid][0] = zmx; rs[wid][1] = zmn; rs[wid][2] = sZc; rs[wid][3] = (float)ic;
    }
    __syncthreads();
    if (threadIdx.x == 0) {
        float tmx = -INF, tmn = INF, tS = 0.f, tC = 0.f;
        #pragma unroll
        for (int w = 0; w < 8; ++w) {
            tmx = fmaxf(tmx, rs[w][0]); tmn = fminf(tmn, rs[w][1]);
            tS += rs[w][2]; tC += rs[w][3];
        }
        atomicMax(&g_acc.zmaxEnc, encf(tmx));
        atomicMin(&g_acc.zminEnc, encf(tmn));
        atomicAdd(&g_acc.sumZc, (double)tS);
        atomicAdd(&g_acc.icnt, (unsigned long long)(int)tC);
    }

    // ---- last-block tail: finalize + reset for next replay ----
    __shared__ unsigned s_last;
    __syncthreads();
    if (threadIdx.x == 0) {
        __threadfence();
        s_last = atomicAdd(&g_tick5, 1u);
    }
    __syncthreads();
    if (s_last != gridDim.x - 1) return;

    if (threadIdx.x == 0) {
        __threadfence();
        unsigned long long cm = __ldcg(&g_acc.cntM); if (cm < 1) cm = 1;
        double cnt = (double)cm;
        float lX = (float)sqrt(__ldcg(&g_acc.sumX) / cnt);
        float lY = (float)sqrt(__ldcg(&g_acc.sumY) / cnt);
        float lZ = (float)sqrt(__ldcg(&g_acc.sumZ) / cnt);
        float rmse_log = (float)(10000.0 * sqrt(__ldcg(&g_acc.sumLog) / cnt));
        float loss17 = rmse_log * fabsf(10.0f * (3.0f - expf(lX) - expf(lY) - expf(lZ)));

        unsigned long long icu = __ldcg(&g_acc.icnt); if (icu < 1) icu = 1;
        double icnt = (double)icu;
        double meanZc = __ldcg(&g_acc.sumZc) / icnt;
        float zmax = decf(__ldcg(&g_acc.zmaxEnc));
        float zmin = decf(__ldcg(&g_acc.zminEnc));
        float below = (float)((double)zmax - meanZc);
        float above = (float)(meanZc - (double)zmin);
        if (above == 0.0f) above = 1e-7f;
        float pmdg = 1000.0f * (above + below);
        float loss_curv = loss17 + pmdg;

        float vals[7] = { rmse_log, lX, lY, lZ, pmdg, loss17, loss_curv };
        for (int j = 0; j < 7 && j < out_size; ++j) out[j] = vals[j];

        // reset accumulators for next graph replay
        g_acc.sumX = 0.0; g_acc.sumY = 0.0; g_acc.sumZ = 0.0; g_acc.sumLog = 0.0;
        g_acc.cntM = 0ull;
        g_acc.gmaxBits = 0;
        g_acc.zmaxEnc = ENC_NEG_INF;
        g_acc.zminEnc = ENC_POS_INF;
        g_acc.icnt = 0ull;
        g_acc.sumZc = 0.0;
        g_tick5 = 0u;
    }
}

// ----------------------------- launch -------------------------------------
extern "C" void kernel_launch(void* const* d_in, const int* in_sizes, int n_in,
                              void* d_out, int out_size) {
    const float* fake = (const float*)d_in[0];
    const float* real = (const float*)d_in[1];
    const int* epoch = (const int*)d_in[2];
    (void)in_sizes; (void)n_in;

    k1_stats<<<PIX_BLOCKS, 256>>>(fake, real);
    k2_planes<<<4, 256>>>(epoch);
    k3_count<<<K3_BLOCKS, K3_THREADS>>>();
    k5_stats<<<PIX_BLOCKS, 256>>>((float*)d_out, out_size);
}

// round 6
// speedup vs baseline: 1.0992x; 1.0992x over previous
#include <cuda_runtime.h>
#include <math.h>
#include <stdint.h>

// ---------------------------------------------------------------------------
// DDDDepthDiff R6: float4 per-pixel kernels (225 blocks), k3 @ PPT=2 + tails
// ---------------------------------------------------------------------------

#define HW       230400       // 360*640
#define WIDTH    640
#define NPLANES  1000
#define MINPTS   5000
#define SPAN     230400u

#define PIX4_BLOCKS (HW / (256 * 4))   // 225
#define K3_CHUNK   512
#define K3_XBLOCKS (HW / K3_CHUNK)     // 450
#define K3_YBLOCKS 2
#define K3_TOTAL   (K3_XBLOCKS * K3_YBLOCKS)   // 900
#define K3_THREADS 256
#define PPT        2

typedef unsigned long long u64;

// ----------------------------- scratch ------------------------------------
__device__ __align__(16) float g_cx[HW];
__device__ __align__(16) float g_cy[HW];
__device__ __align__(16) float g_cz[HW];
__device__ float4 g_planes[NPLANES];
__device__ unsigned g_counts[NPLANES];   // zero-init; k3 tail re-zeros
__device__ unsigned g_tick3, g_tick5;    // zero-init; tails reset

#define ENC_NEG_INF 0x007FFFFFu
#define ENC_POS_INF 0xFF800000u

struct Accum {
    double sumX, sumY, sumZ, sumLog;
    unsigned long long cntM;
    int gmaxBits;
    unsigned zmaxEnc, zminEnc;
    unsigned long long icnt;
    double sumZc;
    float4 bestPlane;
    float R20, R21, R22, dz, thresh;
};
__device__ Accum g_acc = { 0.0, 0.0, 0.0, 0.0, 0ull, 0,
                           ENC_NEG_INF, ENC_POS_INF, 0ull, 0.0,
                           {0.f,0.f,0.f,0.f}, 0.f,0.f,0.f,0.f,0.f };

// ----------------------------- helpers ------------------------------------
__device__ __forceinline__ unsigned encf(float f) {
    unsigned u = __float_as_uint(f);
    return (u & 0x80000000u) ? ~u : (u | 0x80000000u);
}
__device__ __forceinline__ float decf(unsigned e) {
    return (e & 0x80000000u) ? __uint_as_float(e ^ 0x80000000u) : __uint_as_float(~e);
}

__device__ __forceinline__ float wred_add_f(float v) {
    #pragma unroll
    for (int o = 16; o; o >>= 1) v += __shfl_down_sync(0xffffffffu, v, o);
    return v;
}
__device__ __forceinline__ int wred_add_i(int v) {
    #pragma unroll
    for (int o = 16; o; o >>= 1) v += __shfl_down_sync(0xffffffffu, v, o);
    return v;
}
__device__ __forceinline__ float wred_max_f(float v) {
    #pragma unroll
    for (int o = 16; o; o >>= 1) v = fmaxf(v, __shfl_down_sync(0xffffffffu, v, o));
    return v;
}
__device__ __forceinline__ float wred_min_f(float v) {
    #pragma unroll
    for (int o = 16; o; o >>= 1) v = fminf(v, __shfl_down_sync(0xffffffffu, v, o));
    return v;
}
__device__ __forceinline__ int wred_max_i(int v) {
    #pragma unroll
    for (int o = 16; o; o >>= 1) v = max(v, __shfl_down_sync(0xffffffffu, v, o));
    return v;
}

// packed f32x2 ops (sm_103a FFMA2 path — only reachable via PTX)
__device__ __forceinline__ u64 pack2(float lo, float hi) {
    u64 r; asm("mov.b64 %0, {%1, %2};" : "=l"(r) : "f"(lo), "f"(hi)); return r;
}
__device__ __forceinline__ u64 fma2(u64 a, u64 b, u64 c) {
    u64 d; asm("fma.rn.f32x2 %0, %1, %2, %3;" : "=l"(d) : "l"(a), "l"(b), "l"(c)); return d;
}
__device__ __forceinline__ void unpack2(u64 v, unsigned& lo, unsigned& hi) {
    asm("mov.b64 {%0, %1}, %2;" : "=r"(lo), "=r"(hi) : "l"(v));
}

// ---- threefry-2x32 (JAX partitionable mode), keys folded at compile time ---
struct TFOut { unsigned x0, x1; };
constexpr unsigned rotl32(unsigned x, unsigned r) { return (x << r) | (x >> (32u - r)); }
constexpr TFOut tf_const(unsigned k0, unsigned k1, unsigned x0, unsigned x1) {
    unsigned ks0 = k0, ks1 = k1, ks2 = 0x1BD11BDAu ^ k0 ^ k1;
    const unsigned rA[4] = { 13u, 15u, 26u, 6u };
    const unsigned rB[4] = { 17u, 29u, 16u, 24u };
    x0 += ks0; x1 += ks1;
    for (int i = 0; i < 5; ++i) {
        for (int j = 0; j < 4; ++j) {
            unsigned r = ((i & 1) == 0) ? rA[j] : rB[j];
            x0 += x1; x1 = rotl32(x1, r); x1 ^= x0;
        }
        const unsigned kss[3] = { ks0, ks1, ks2 };
        x0 += kss[(i + 1) % 3];
        x1 += kss[(i + 2) % 3] + (unsigned)(i + 1);
    }
    return { x0, x1 };
}
// key(42)->(0,42); split -> k2 = tf(0,1). randint's multiplier wraps to 0 in
// uint32 (65536^2 mod 2^32 == 0), so idx = lower_bits(k2, i) % SPAN only.
constexpr TFOut KB = tf_const(0u, 42u, 0u, 1u);

__device__ __forceinline__ unsigned tf_bits_lo(unsigned ctr) {
    unsigned x0 = 0u, x1 = ctr;
    unsigned ks[3] = { KB.x0, KB.x1, 0x1BD11BDAu ^ KB.x0 ^ KB.x1 };
    const unsigned rA[4] = { 13u, 15u, 26u, 6u };
    const unsigned rB[4] = { 17u, 29u, 16u, 24u };
    x0 += ks[0]; x1 += ks[1];
    #pragma unroll
    for (int i = 0; i < 5; ++i) {
        #pragma unroll
        for (int j = 0; j < 4; ++j) {
            unsigned r = ((i & 1) == 0) ? rA[j] : rB[j];
            x0 += x1;
            x1 = (x1 << r) | (x1 >> (32u - r));
            x1 ^= x0;
        }
        x0 += ks[(i + 1) % 3];
        x1 += ks[(i + 2) % 3] + (unsigned)(i + 1);
    }
    return x0 ^ x1;
}

// Scalar inlier predicate for k5 — same rounding as the packed path's d.
__device__ __forceinline__ float plane_dist(float4 pl, float px, float py, float pz) {
    return __fmaf_rn(pl.x, px, __fmaf_rn(pl.y, py, __fmaf_rn(pl.z, pz, pl.w)));
}

// ----------------------------- kernel 1 ------------------------------------
// Per-pixel losses + fake cloud. 4 px/thread via float4, 225 blocks.
__global__ __launch_bounds__(256)
void k1_stats(const float4* __restrict__ fake4, const float4* __restrict__ real4) {
    int i4 = blockIdx.x * 256 + threadIdx.x;   // 0..57599
    float4 df4 = fake4[i4];
    float4 dr4 = real4[i4];
    int i0 = i4 * 4;
    int r = i0 / WIDTH;
    int colbase = i0 - r * WIDTH;              // 640 % 4 == 0: no row wrap
    float rr = (float)r - 169.808f;

    float dfv[4] = { df4.x, df4.y, df4.z, df4.w };
    float drv[4] = { dr4.x, dr4.y, dr4.z, dr4.w };
    float oxv[4], oyv[4], ozv[4];

    float sX = 0.f, sY = 0.f, sZ = 0.f, sL = 0.f, mx = 0.f;
    int c = 0;
    #pragma unroll
    for (int j = 0; j < 4; ++j) {
        float cc = (float)(colbase + j) - 334.081f;
        float df = dfv[j], dr = drv[j];
        bool vf = (df > 0.0f) && (df < 65535.0f);
        bool vr = (dr > 0.0f) && (dr < 65535.0f);

        // fake cloud: EXACT divisions (feeds gmax -> plane selection)
        float fz = df / 1000.0f;
        float fxp = (fz * cc) / 460.585f;
        float fyp = (fz * rr) / 460.268f;
        float FXv = fxp * 1000.0f, FYv = fyp * 1000.0f, FZv = fz * 1000.0f;
        if (FXv == 0.0f) FXv = 1e-7f;
        if (FYv == 0.0f) FYv = 1e-7f;
        if (FZv == 0.0f) FZv = 1e-7f;
        float ox = vf ? FXv : 0.0f;
        float oy = vf ? FYv : 0.0f;
        float oz = vf ? FZv : 0.0f;
        oxv[j] = ox; oyv[j] = oy; ozv[j] = oz;
        mx = fmaxf(mx, fmaxf(ox, fmaxf(oy, oz)));

        if (vr && vf) {
            float rz = dr * (1.0f / 1000.0f);
            float rxp = (rz * cc) * (1.0f / 460.585f);
            float ryp = (rz * rr) * (1.0f / 460.268f);
            float RXv = rxp * 1000.0f, RYv = ryp * 1000.0f, RZv = rz * 1000.0f;
            if (RXv == 0.0f) RXv = 1e-7f;
            if (RYv == 0.0f) RYv = 1e-7f;
            if (RZv == 0.0f) RZv = 1e-7f;
            float dx = RXv - FXv, dy = RYv - FYv, dz = RZv - FZv;
            sX += dx * dx; sY += dy * dy; sZ += dz * dz;
            float dl = __logf(fabsf(RZv)) - __logf(fabsf(FZv));
            sL += dl * dl;
            c++;
        }
    }
    ((float4*)g_cx)[i4] = make_float4(oxv[0], oxv[1], oxv[2], oxv[3]);
    ((float4*)g_cy)[i4] = make_float4(oyv[0], oyv[1], oyv[2], oyv[3]);
    ((float4*)g_cz)[i4] = make_float4(ozv[0], ozv[1], ozv[2], ozv[3]);

    sX = wred_add_f(sX); sY = wred_add_f(sY); sZ = wred_add_f(sZ); sL = wred_add_f(sL);
    c = wred_add_i(c);
    mx = wred_max_f(mx);

    __shared__ float rs[8][6];
    int wid = threadIdx.x >> 5;
    if ((threadIdx.x & 31) == 0) {
        rs[wid][0] = sX; rs[wid][1] = sY; rs[wid][2] = sZ;
        rs[wid][3] = sL; rs[wid][4] = (float)c; rs[wid][5] = mx;
    }
    __syncthreads();
    if (threadIdx.x == 0) {
        float tX = 0.f, tY = 0.f, tZ = 0.f, tL = 0.f, tC = 0.f, tM = 0.f;
        #pragma unroll
        for (int w = 0; w < 8; ++w) {
            tX += rs[w][0]; tY += rs[w][1]; tZ += rs[w][2];
            tL += rs[w][3]; tC += rs[w][4]; tM = fmaxf(tM, rs[w][5]);
        }
        atomicAdd(&g_acc.sumX, (double)tX);
        atomicAdd(&g_acc.sumY, (double)tY);
        atomicAdd(&g_acc.sumZ, (double)tZ);
        atomicAdd(&g_acc.sumLog, (double)tL);
        atomicAdd(&g_acc.cntM, (unsigned long long)(int)tC);
        atomicMax(&g_acc.gmaxBits, __float_as_int(tM));   // tM >= 0
    }
}

// ----------------------------- kernel 2 ------------------------------------
// Threshold + 1000 plane hypotheses.
__global__ __launch_bounds__(256)
void k2_planes(const int* __restrict__ epoch_ptr) {
    int t = blockIdx.x * 256 + threadIdx.x;
    if (t == 0) {
        int epoch = epoch_ptr[0];
        float thf = (float)(0.025 - 0.001 * (double)epoch);
        g_acc.thresh = fmaxf(thf, 0.005f);
    }
    if (t >= NPLANES) return;

    int ids[3];
    #pragma unroll
    for (int j = 0; j < 3; ++j)
        ids[j] = (int)(tf_bits_lo((unsigned)(t * 3 + j)) % SPAN);

    float gmax = __int_as_float(g_acc.gmaxBits);
    float p0x = g_cx[ids[0]] / gmax, p0y = g_cy[ids[0]] / gmax, p0z = g_cz[ids[0]] / gmax;
    float p1x = g_cx[ids[1]] / gmax, p1y = g_cy[ids[1]] / gmax, p1z = g_cz[ids[1]] / gmax;
    float p2x = g_cx[ids[2]] / gmax, p2y = g_cy[ids[2]] / gmax, p2z = g_cz[ids[2]] / gmax;

    float ax = p1x - p0x, ay = p1y - p0y, az = p1z - p0z;
    float bx = p2x - p0x, by = p2y - p0y, bz = p2z - p0z;
    float nx = ay * bz - az * by;
    float ny = az * bx - ax * bz;
    float nz = ax * by - ay * bx;
    float nn = sqrtf(nx * nx + ny * ny + nz * nz);
    nx /= nn; ny /= nn; nz /= nn;
    float kk = -(nx * p1x + ny * p1y + nz * p1z);
    g_planes[t] = make_float4(nx, ny, nz, kk);
}

// ----------------------------- kernel 3 ------------------------------------
// Packed f32x2 inlier counting (PPT=2, grid 450x2); tail: selection + reset.
__global__ __launch_bounds__(K3_THREADS)
void k3_count() {
    __shared__ __align__(16) u64 sx2[K3_CHUNK / 2];
    __shared__ __align__(16) u64 sy2[K3_CHUNK / 2];
    __shared__ __align__(16) u64 sz2[K3_CHUNK / 2];

    int base = blockIdx.x * K3_CHUNK;
    float gmax = __int_as_float(g_acc.gmaxBits);
    float th = g_acc.thresh;
    u64 NEGTH2 = pack2(-th * th, -th * th);

    {
        int j = threadIdx.x;           // K3_CHUNK/2 == K3_THREADS
        float2 vx = ((const float2*)(g_cx + base))[j];
        float2 vy = ((const float2*)(g_cy + base))[j];
        float2 vz = ((const float2*)(g_cz + base))[j];
        ((float2*)sx2)[j] = make_float2(vx.x / gmax, vx.y / gmax);
        ((float2*)sy2)[j] = make_float2(vy.x / gmax, vy.y / gmax);
        ((float2*)sz2)[j] = make_float2(vz.x / gmax, vz.y / gmax);
    }

    int pbase = blockIdx.y * 512;
    u64 PX[PPT], PY[PPT], PZ[PPT], PW[PPT];
    unsigned cnt[PPT];
    int pid[PPT];
    #pragma unroll
    for (int k = 0; k < PPT; ++k) {
        pid[k] = pbase + threadIdx.x + k * K3_THREADS;
        float4 pl = (pid[k] < NPLANES) ? g_planes[pid[k]]
                                       : make_float4(0.0f, 0.0f, 0.0f, 1e18f);
        PX[k] = pack2(pl.x, pl.x);
        PY[k] = pack2(pl.y, pl.y);
        PZ[k] = pack2(pl.z, pl.z);
        PW[k] = pack2(pl.w, pl.w);
        cnt[k] = 0u;
    }
    __syncthreads();

    const ulonglong2* sxv = (const ulonglong2*)sx2;   // 128 entries
    const ulonglong2* syv = (const ulonglong2*)sy2;
    const ulonglong2* szv = (const ulonglong2*)sz2;

    #pragma unroll 8
    for (int jj = 0; jj < K3_CHUNK / 4; ++jj) {
        ulonglong2 X2 = sxv[jj];                       // LDS.128 broadcast
        ulonglong2 Y2 = syv[jj];
        ulonglong2 Z2 = szv[jj];
        #pragma unroll
        for (int k = 0; k < PPT; ++k) {
            u64 d0 = fma2(PX[k], X2.x, fma2(PY[k], Y2.x, fma2(PZ[k], Z2.x, PW[k])));
            u64 u0 = fma2(d0, d0, NEGTH2);
            unsigned lo0, hi0; unpack2(u0, lo0, hi0);
            cnt[k] += (lo0 >> 31) + (hi0 >> 31);
            u64 d1 = fma2(PX[k], X2.y, fma2(PY[k], Y2.y, fma2(PZ[k], Z2.y, PW[k])));
            u64 u1 = fma2(d1, d1, NEGTH2);
            unsigned lo1, hi1; unpack2(u1, lo1, hi1);
            cnt[k] += (lo1 >> 31) + (hi1 >> 31);
        }
    }

    #pragma unroll
    for (int k = 0; k < PPT; ++k)
        if (pid[k] < NPLANES) atomicAdd(&g_counts[pid[k]], cnt[k]);

    // ---- last-block tail (of 900): selection + rotation + counts reset ----
    __shared__ unsigned s_last;
    __syncthreads();
    if (threadIdx.x == 0) {
        __threadfence();
        s_last = atomicAdd(&g_tick3, 1u);
    }
    __syncthreads();
    if (s_last != K3_TOTAL - 1) return;
    __threadfence();

    int best_key = -1;
    #pragma unroll
    for (int k = 0; k < 4; ++k) {
        int t = threadIdx.x + k * K3_THREADS;
        if (t < NPLANES) {
            int cc = (int)__ldcg(&g_counts[t]);
            int score = (cc > MINPTS) ? cc : -1;
            best_key = max(best_key, ((score + 1) << 12) | (1023 - t));
        }
    }
    best_key = wred_max_i(best_key);
    __shared__ int skey[8];
    int wid = threadIdx.x >> 5;
    if ((threadIdx.x & 31) == 0) skey[wid] = best_key;
    __syncthreads();
    #pragma unroll
    for (int k = 0; k < 4; ++k) {
        int t = threadIdx.x + k * K3_THREADS;
        if (t < NPLANES) g_counts[t] = 0u;            // reset for next replay
    }
    if (threadIdx.x == 0) {
        int mk = skey[0];
        #pragma unroll
        for (int w = 1; w < 8; ++w) mk = max(mk, skey[w]);
        int best = 1023 - (mk & 0xFFF);
        float4 bp = g_planes[best];
        g_acc.bestPlane = bp;
        float a = bp.x, b = bp.y, c = bp.z, d = bp.w;
        float n2 = a * a + b * b + c * c;
        float cos_t = c / sqrtf(n2);
        float sin_t = sqrtf((a * a + b * b) / n2);
        float sab = sqrtf(a * a + b * b);
        float u1 = b / sab;
        float u2 = -a / sab;
        g_acc.dz = d / c;
        g_acc.R20 = -u2 * sin_t;
        g_acc.R21 = u1 * sin_t;
        g_acc.R22 = cos_t;
        g_tick3 = 0u;
    }
}

// ----------------------------- kernel 5 ------------------------------------
// Inlier z stats, 4 px/thread (float4), 225 blocks; tail: finalize + reset.
__global__ __launch_bounds__(256)
void k5_stats(float* __restrict__ out, int out_size) {
    int i4 = blockIdx.x * 256 + threadIdx.x;
    float gmax = __int_as_float(g_acc.gmaxBits);
    float th = g_acc.thresh;
    float4 bp = g_acc.bestPlane;
    float R20 = g_acc.R20, R21 = g_acc.R21, R22 = g_acc.R22, dz = g_acc.dz;
    const float INF = __int_as_float(0x7f800000);

    float4 vx = ((const float4*)g_cx)[i4];
    float4 vy = ((const float4*)g_cy)[i4];
    float4 vz = ((const float4*)g_cz)[i4];
    float pxv[4] = { vx.x, vx.y, vx.z, vx.w };
    float pyv[4] = { vy.x, vy.y, vy.z, vy.w };
    float pzv[4] = { vz.x, vz.y, vz.z, vz.w };

    float zmx = -INF, zmn = INF, sZc = 0.f;
    int ic = 0;
    #pragma unroll
    for (int j = 0; j < 4; ++j) {
        float px = pxv[j] / gmax, py = pyv[j] / gmax, pz = pzv[j] / gmax;
        float d = plane_dist(bp, px, py, pz);
        bool in = (fabsf(d) <= th);
        float zc = __fmaf_rn(pz + dz, R22, __fmaf_rn(py, R21, px * R20));
        if (in) {
            zmx = fmaxf(zmx, zc);
            zmn = fminf(zmn, zc);
            sZc += zc;
            ic++;
        }
    }

    zmx = wred_max_f(zmx);
    zmn = wred_min_f(zmn);
    sZc = wred_add_f(sZc);
    ic = wred_add_i(ic);

    __shared__ float rs[8][4];
    int wid = threadIdx.x >> 5;
    if ((threadIdx.x & 31) == 0) {
        rs[wid][0] = zmx; rs[wid][1] = zmn; rs[wid][2] = sZc; rs[wid][3] = (float)ic;
    }
    __syncthreads();
    if (threadIdx.x == 0) {
        float tmx = -INF, tmn = INF, tS = 0.f, tC = 0.f;
        #pragma unroll
        for (int w = 0; w < 8; ++w) {
            tmx = fmaxf(tmx, rs[w][0]); tmn = fminf(tmn, rs[w][1]);
            tS += rs[w][2]; tC += rs[w][3];
        }
        atomicMax(&g_acc.zmaxEnc, encf(tmx));
        atomicMin(&g_acc.zminEnc, encf(tmn));
        atomicAdd(&g_acc.sumZc, (double)tS);
        atomicAdd(&g_acc.icnt, (unsigned long long)(int)tC);
    }

    // ---- last-block tail (of 225): finalize + reset for next replay ----
    __shared__ unsigned s_last;
    __syncthreads();
    if (threadIdx.x == 0) {
        __threadfence();
        s_last = atomicAdd(&g_tick5, 1u);
    }
    __syncthreads();
    if (s_last != PIX4_BLOCKS - 1) return;

    if (threadIdx.x == 0) {
        __threadfence();
        unsigned long long cm = __ldcg(&g_acc.cntM); if (cm < 1) cm = 1;
        double cnt = (double)cm;
        float lX = (float)sqrt(__ldcg(&g_acc.sumX) / cnt);
        float lY = (float)sqrt(__ldcg(&g_acc.sumY) / cnt);
        float lZ = (float)sqrt(__ldcg(&g_acc.sumZ) / cnt);
        float rmse_log = (float)(10000.0 * sqrt(__ldcg(&g_acc.sumLog) / cnt));
        float loss17 = rmse_log * fabsf(10.0f * (3.0f - expf(lX) - expf(lY) - expf(lZ)));

        unsigned long long icu = __ldcg(&g_acc.icnt); if (icu < 1) icu = 1;
        double icnt = (double)icu;
        double meanZc = __ldcg(&g_acc.sumZc) / icnt;
        float zmax = decf(__ldcg(&g_acc.zmaxEnc));
        float zmin = decf(__ldcg(&g_acc.zminEnc));
        float below = (float)((double)zmax - meanZc);
        float above = (float)(meanZc - (double)zmin);
        if (above == 0.0f) above = 1e-7f;
        float pmdg = 1000.0f * (above + below);
        float loss_curv = loss17 + pmdg;

        float vals[7] = { rmse_log, lX, lY, lZ, pmdg, loss17, loss_curv };
        for (int j = 0; j < 7 && j < out_size; ++j) out[j] = vals[j];

        // reset accumulators for next graph replay
        g_acc.sumX = 0.0; g_acc.sumY = 0.0; g_acc.sumZ = 0.0; g_acc.sumLog = 0.0;
        g_acc.cntM = 0ull;
        g_acc.gmaxBits = 0;
        g_acc.zmaxEnc = ENC_NEG_INF;
        g_acc.zminEnc = ENC_POS_INF;
        g_acc.icnt = 0ull;
        g_acc.sumZc = 0.0;
        g_tick5 = 0u;
    }
}

// ----------------------------- launch -------------------------------------
extern "C" void kernel_launch(void* const* d_in, const int* in_sizes, int n_in,
                              void* d_out, int out_size) {
    const float4* fake4 = (const float4*)d_in[0];
    const float4* real4 = (const float4*)d_in[1];
    const int* epoch = (const int*)d_in[2];
    (void)in_sizes; (void)n_in;

    k1_stats<<<PIX4_BLOCKS, 256>>>(fake4, real4);
    k2_planes<<<4, 256>>>(epoch);
    dim3 g3(K3_XBLOCKS, K3_YBLOCKS);
    k3_count<<<g3, K3_THREADS>>>();
    k5_stats<<<PIX4_BLOCKS, 256>>>((float*)d_out, out_size);
}

// round 8
// speedup vs baseline: 1.1771x; 1.0708x over previous
#include <cuda_runtime.h>
#include <math.h>
#include <stdint.h>

// ---------------------------------------------------------------------------
// DDDDepthDiff R7: all precise FDIVs replaced by reciprocal multiplies
// (consistent invg normalization across k2/k3/k5); shapes kept from R6.
// ---------------------------------------------------------------------------

#define HW       230400       // 360*640
#define WIDTH    640
#define NPLANES  1000
#define MINPTS   5000
#define SPAN     230400u

#define PIX4_BLOCKS (HW / (256 * 4))   // 225
#define K3_CHUNK   512
#define K3_XBLOCKS (HW / K3_CHUNK)     // 450
#define K3_YBLOCKS 2
#define K3_TOTAL   (K3_XBLOCKS * K3_YBLOCKS)   // 900
#define K3_THREADS 256
#define PPT        2

#define C_INV1000  (1.0f / 1000.0f)
#define C_INVFX    (1.0f / 460.585f)
#define C_INVFY    (1.0f / 460.268f)

typedef unsigned long long u64;

// ----------------------------- scratch ------------------------------------
__device__ __align__(16) float g_cx[HW];
__device__ __align__(16) float g_cy[HW];
__device__ __align__(16) float g_cz[HW];
__device__ float4 g_planes[NPLANES];
__device__ unsigned g_counts[NPLANES];   // zero-init; k3 tail re-zeros
__device__ unsigned g_tick3, g_tick5;    // zero-init; tails reset

#define ENC_NEG_INF 0x007FFFFFu
#define ENC_POS_INF 0xFF800000u

struct Accum {
    double sumX, sumY, sumZ, sumLog;
    unsigned long long cntM;
    int gmaxBits;
    unsigned zmaxEnc, zminEnc;
    unsigned long long icnt;
    double sumZc;
    float4 bestPlane;
    float R20, R21, R22, dz, thresh;
};
__device__ Accum g_acc = { 0.0, 0.0, 0.0, 0.0, 0ull, 0,
                           ENC_NEG_INF, ENC_POS_INF, 0ull, 0.0,
                           {0.f,0.f,0.f,0.f}, 0.f,0.f,0.f,0.f,0.f };

// ----------------------------- helpers ------------------------------------
__device__ __forceinline__ unsigned encf(float f) {
    unsigned u = __float_as_uint(f);
    return (u & 0x80000000u) ? ~u : (u | 0x80000000u);
}
__device__ __forceinline__ float decf(unsigned e) {
    return (e & 0x80000000u) ? __uint_as_float(e ^ 0x80000000u) : __uint_as_float(~e);
}

__device__ __forceinline__ float wred_add_f(float v) {
    #pragma unroll
    for (int o = 16; o; o >>= 1) v += __shfl_down_sync(0xffffffffu, v, o);
    return v;
}
__device__ __forceinline__ int wred_add_i(int v) {
    #pragma unroll
    for (int o = 16; o; o >>= 1) v += __shfl_down_sync(0xffffffffu, v, o);
    return v;
}
__device__ __forceinline__ float wred_max_f(float v) {
    #pragma unroll
    for (int o = 16; o; o >>= 1) v = fmaxf(v, __shfl_down_sync(0xffffffffu, v, o));
    return v;
}
__device__ __forceinline__ float wred_min_f(float v) {
    #pragma unroll
    for (int o = 16; o; o >>= 1) v = fminf(v, __shfl_down_sync(0xffffffffu, v, o));
    return v;
}
__device__ __forceinline__ int wred_max_i(int v) {
    #pragma unroll
    for (int o = 16; o; o >>= 1) v = max(v, __shfl_down_sync(0xffffffffu, v, o));
    return v;
}

// packed f32x2 ops (sm_103a FFMA2 path — only reachable via PTX)
__device__ __forceinline__ u64 pack2(float lo, float hi) {
    u64 r; asm("mov.b64 %0, {%1, %2};" : "=l"(r) : "f"(lo), "f"(hi)); return r;
}
__device__ __forceinline__ u64 fma2(u64 a, u64 b, u64 c) {
    u64 d; asm("fma.rn.f32x2 %0, %1, %2, %3;" : "=l"(d) : "l"(a), "l"(b), "l"(c)); return d;
}
__device__ __forceinline__ void unpack2(u64 v, unsigned& lo, unsigned& hi) {
    asm("mov.b64 {%0, %1}, %2;" : "=r"(lo), "=r"(hi) : "l"(v));
}

// ---- threefry-2x32 (JAX partitionable mode), keys folded at compile time ---
struct TFOut { unsigned x0, x1; };
constexpr unsigned rotl32(unsigned x, unsigned r) { return (x << r) | (x >> (32u - r)); }
constexpr TFOut tf_const(unsigned k0, unsigned k1, unsigned x0, unsigned x1) {
    unsigned ks0 = k0, ks1 = k1, ks2 = 0x1BD11BDAu ^ k0 ^ k1;
    const unsigned rA[4] = { 13u, 15u, 26u, 6u };
    const unsigned rB[4] = { 17u, 29u, 16u, 24u };
    x0 += ks0; x1 += ks1;
    for (int i = 0; i < 5; ++i) {
        for (int j = 0; j < 4; ++j) {
            unsigned r = ((i & 1) == 0) ? rA[j] : rB[j];
            x0 += x1; x1 = rotl32(x1, r); x1 ^= x0;
        }
        const unsigned kss[3] = { ks0, ks1, ks2 };
        x0 += kss[(i + 1) % 3];
        x1 += kss[(i + 2) % 3] + (unsigned)(i + 1);
    }
    return { x0, x1 };
}
// key(42)->(0,42); split -> k2 = tf(0,1). randint's multiplier wraps to 0 in
// uint32 (65536^2 mod 2^32 == 0), so idx = lower_bits(k2, i) % SPAN only.
constexpr TFOut KB = tf_const(0u, 42u, 0u, 1u);

__device__ __forceinline__ unsigned tf_bits_lo(unsigned ctr) {
    unsigned x0 = 0u, x1 = ctr;
    unsigned ks[3] = { KB.x0, KB.x1, 0x1BD11BDAu ^ KB.x0 ^ KB.x1 };
    const unsigned rA[4] = { 13u, 15u, 26u, 6u };
    const unsigned rB[4] = { 17u, 29u, 16u, 24u };
    x0 += ks[0]; x1 += ks[1];
    #pragma unroll
    for (int i = 0; i < 5; ++i) {
        #pragma unroll
        for (int j = 0; j < 4; ++j) {
            unsigned r = ((i & 1) == 0) ? rA[j] : rB[j];
            x0 += x1;
            x1 = (x1 << r) | (x1 >> (32u - r));
            x1 ^= x0;
        }
        x0 += ks[(i + 1) % 3];
        x1 += ks[(i + 2) % 3] + (unsigned)(i + 1);
    }
    return x0 ^ x1;
}

// Scalar inlier predicate for k5 — same rounding as the packed path's d.
__device__ __forceinline__ float plane_dist(float4 pl, float px, float py, float pz) {
    return __fmaf_rn(pl.x, px, __fmaf_rn(pl.y, py, __fmaf_rn(pl.z, pz, pl.w)));
}

// ----------------------------- kernel 1 ------------------------------------
// Per-pixel losses + fake cloud. 4 px/thread via float4, 225 blocks.
// All divides-by-constants replaced by reciprocal multiplies.
__global__ __launch_bounds__(256)
void k1_stats(const float4* __restrict__ fake4, const float4* __restrict__ real4) {
    int i4 = blockIdx.x * 256 + threadIdx.x;   // 0..57599
    float4 df4 = fake4[i4];
    float4 dr4 = real4[i4];
    int i0 = i4 * 4;
    int r = i0 / WIDTH;
    int colbase = i0 - r * WIDTH;              // 640 % 4 == 0: no row wrap
    float rr = (float)r - 169.808f;

    float dfv[4] = { df4.x, df4.y, df4.z, df4.w };
    float drv[4] = { dr4.x, dr4.y, dr4.z, dr4.w };
    float oxv[4], oyv[4], ozv[4];

    float sX = 0.f, sY = 0.f, sZ = 0.f, sL = 0.f, mx = 0.f;
    int c = 0;
    #pragma unroll
    for (int j = 0; j < 4; ++j) {
        float cc = (float)(colbase + j) - 334.081f;
        float df = dfv[j], dr = drv[j];
        bool vf = (df > 0.0f) && (df < 65535.0f);
        bool vr = (dr > 0.0f) && (dr < 65535.0f);

        float fz = df * C_INV1000;
        float fxp = (fz * cc) * C_INVFX;
        float fyp = (fz * rr) * C_INVFY;
        float FXv = fxp * 1000.0f, FYv = fyp * 1000.0f, FZv = fz * 1000.0f;
        if (FXv == 0.0f) FXv = 1e-7f;
        if (FYv == 0.0f) FYv = 1e-7f;
        if (FZv == 0.0f) FZv = 1e-7f;
        float ox = vf ? FXv : 0.0f;
        float oy = vf ? FYv : 0.0f;
        float oz = vf ? FZv : 0.0f;
        oxv[j] = ox; oyv[j] = oy; ozv[j] = oz;
        mx = fmaxf(mx, fmaxf(ox, fmaxf(oy, oz)));

        if (vr && vf) {
            float rz = dr * C_INV1000;
            float rxp = (rz * cc) * C_INVFX;
            float ryp = (rz * rr) * C_INVFY;
            float RXv = rxp * 1000.0f, RYv = ryp * 1000.0f, RZv = rz * 1000.0f;
            if (RXv == 0.0f) RXv = 1e-7f;
            if (RYv == 0.0f) RYv = 1e-7f;
            if (RZv == 0.0f) RZv = 1e-7f;
            float dx = RXv - FXv, dy = RYv - FYv, dz = RZv - FZv;
            sX += dx * dx; sY += dy * dy; sZ += dz * dz;
            float dl = __logf(fabsf(RZv)) - __logf(fabsf(FZv));
            sL += dl * dl;
            c++;
        }
    }
    ((float4*)g_cx)[i4] = make_float4(oxv[0], oxv[1], oxv[2], oxv[3]);
    ((float4*)g_cy)[i4] = make_float4(oyv[0], oyv[1], oyv[2], oyv[3]);
    ((float4*)g_cz)[i4] = make_float4(ozv[0], ozv[1], ozv[2], ozv[3]);

    sX = wred_add_f(sX); sY = wred_add_f(sY); sZ = wred_add_f(sZ); sL = wred_add_f(sL);
    c = wred_add_i(c);
    mx = wred_max_f(mx);

    __shared__ float rs[8][6];
    int wid = threadIdx.x >> 5;
    if ((threadIdx.x & 31) == 0) {
        rs[wid][0] = sX; rs[wid][1] = sY; rs[wid][2] = sZ;
        rs[wid][3] = sL; rs[wid][4] = (float)c; rs[wid][5] = mx;
    }
    __syncthreads();
    if (threadIdx.x == 0) {
        float tX = 0.f, tY = 0.f, tZ = 0.f, tL = 0.f, tC = 0.f, tM = 0.f;
        #pragma unroll
        for (int w = 0; w < 8; ++w) {
            tX += rs[w][0]; tY += rs[w][1]; tZ += rs[w][2];
            tL += rs[w][3]; tC += rs[w][4]; tM = fmaxf(tM, rs[w][5]);
        }
        atomicAdd(&g_acc.sumX, (double)tX);
        atomicAdd(&g_acc.sumY, (double)tY);
        atomicAdd(&g_acc.sumZ, (double)tZ);
        atomicAdd(&g_acc.sumLog, (double)tL);
        atomicAdd(&g_acc.cntM, (unsigned long long)(int)tC);
        atomicMax(&g_acc.gmaxBits, __float_as_int(tM));   // tM >= 0
    }
}

// ----------------------------- kernel 2 ------------------------------------
// Threshold + 1000 plane hypotheses (invg normalization, shared with k3/k5).
__global__ __launch_bounds__(256)
void k2_planes(const int* __restrict__ epoch_ptr) {
    int t = blockIdx.x * 256 + threadIdx.x;
    if (t == 0) {
        int epoch = epoch_ptr[0];
        float thf = (float)(0.025 - 0.001 * (double)epoch);
        g_acc.thresh = fmaxf(thf, 0.005f);
    }
    if (t >= NPLANES) return;

    int ids[3];
    #pragma unroll
    for (int j = 0; j < 3; ++j)
        ids[j] = (int)(tf_bits_lo((unsigned)(t * 3 + j)) % SPAN);

    float invg = 1.0f / __int_as_float(g_acc.gmaxBits);
    float p0x = g_cx[ids[0]] * invg, p0y = g_cy[ids[0]] * invg, p0z = g_cz[ids[0]] * invg;
    float p1x = g_cx[ids[1]] * invg, p1y = g_cy[ids[1]] * invg, p1z = g_cz[ids[1]] * invg;
    float p2x = g_cx[ids[2]] * invg, p2y = g_cy[ids[2]] * invg, p2z = g_cz[ids[2]] * invg;

    float ax = p1x - p0x, ay = p1y - p0y, az = p1z - p0z;
    float bx = p2x - p0x, by = p2y - p0y, bz = p2z - p0z;
    float nx = ay * bz - az * by;
    float ny = az * bx - ax * bz;
    float nz = ax * by - ay * bx;
    float nn = sqrtf(nx * nx + ny * ny + nz * nz);
    nx /= nn; ny /= nn; nz /= nn;
    float kk = -(nx * p1x + ny * p1y + nz * p1z);
    g_planes[t] = make_float4(nx, ny, nz, kk);
}

// ----------------------------- kernel 3 ------------------------------------
// Packed f32x2 inlier counting (PPT=2, grid 450x2); tail: selection + reset.
__global__ __launch_bounds__(K3_THREADS)
void k3_count() {
    __shared__ __align__(16) u64 sx2[K3_CHUNK / 2];
    __shared__ __align__(16) u64 sy2[K3_CHUNK / 2];
    __shared__ __align__(16) u64 sz2[K3_CHUNK / 2];

    int base = blockIdx.x * K3_CHUNK;
    float invg = 1.0f / __int_as_float(g_acc.gmaxBits);
    float th = g_acc.thresh;
    u64 NEGTH2 = pack2(-th * th, -th * th);

    {
        int j = threadIdx.x;           // K3_CHUNK/2 == K3_THREADS
        float2 vx = ((const float2*)(g_cx + base))[j];
        float2 vy = ((const float2*)(g_cy + base))[j];
        float2 vz = ((const float2*)(g_cz + base))[j];
        ((float2*)sx2)[j] = make_float2(vx.x * invg, vx.y * invg);
        ((float2*)sy2)[j] = make_float2(vy.x * invg, vy.y * invg);
        ((float2*)sz2)[j] = make_float2(vz.x * invg, vz.y * invg);
    }

    int pbase = blockIdx.y * 512;
    u64 PX[PPT], PY[PPT], PZ[PPT], PW[PPT];
    unsigned cnt[PPT];
    int pid[PPT];
    #pragma unroll
    for (int k = 0; k < PPT; ++k) {
        pid[k] = pbase + threadIdx.x + k * K3_THREADS;
        float4 pl = (pid[k] < NPLANES) ? g_planes[pid[k]]
                                       : make_float4(0.0f, 0.0f, 0.0f, 1e18f);
        PX[k] = pack2(pl.x, pl.x);
        PY[k] = pack2(pl.y, pl.y);
        PZ[k] = pack2(pl.z, pl.z);
        PW[k] = pack2(pl.w, pl.w);
        cnt[k] = 0u;
    }
    __syncthreads();

    const ulonglong2* sxv = (const ulonglong2*)sx2;   // 128 entries
    const ulonglong2* syv = (const ulonglong2*)sy2;
    const ulonglong2* szv = (const ulonglong2*)sz2;

    #pragma unroll 8
    for (int jj = 0; jj < K3_CHUNK / 4; ++jj) {
        ulonglong2 X2 = sxv[jj];                       // LDS.128 broadcast
        ulonglong2 Y2 = syv[jj];
        ulonglong2 Z2 = szv[jj];
        #pragma unroll
        for (int k = 0; k < PPT; ++k) {
            u64 d0 = fma2(PX[k], X2.x, fma2(PY[k], Y2.x, fma2(PZ[k], Z2.x, PW[k])));
            u64 u0 = fma2(d0, d0, NEGTH2);
            unsigned lo0, hi0; unpack2(u0, lo0, hi0);
            cnt[k] += (lo0 >> 31) + (hi0 >> 31);
            u64 d1 = fma2(PX[k], X2.y, fma2(PY[k], Y2.y, fma2(PZ[k], Z2.y, PW[k])));
            u64 u1 = fma2(d1, d1, NEGTH2);
            unsigned lo1, hi1; unpack2(u1, lo1, hi1);
            cnt[k] += (lo1 >> 31) + (hi1 >> 31);
        }
    }

    #pragma unroll
    for (int k = 0; k < PPT; ++k)
        if (pid[k] < NPLANES) atomicAdd(&g_counts[pid[k]], cnt[k]);

    // ---- last-block tail (of 900): selection + rotation + counts reset ----
    __shared__ unsigned s_last;
    __syncthreads();
    if (threadIdx.x == 0) {
        __threadfence();
        s_last = atomicAdd(&g_tick3, 1u);
    }
    __syncthreads();
    if (s_last != K3_TOTAL - 1) return;
    __threadfence();

    int best_key = -1;
    #pragma unroll
    for (int k = 0; k < 4; ++k) {
        int t = threadIdx.x + k * K3_THREADS;
        if (t < NPLANES) {
            int cc = (int)__ldcg(&g_counts[t]);
            int score = (cc > MINPTS) ? cc : -1;
            best_key = max(best_key, ((score + 1) << 12) | (1023 - t));
        }
    }
    best_key = wred_max_i(best_key);
    __shared__ int skey[8];
    int wid = threadIdx.x >> 5;
    if ((threadIdx.x & 31) == 0) skey[wid] = best_key;
    __syncthreads();
    #pragma unroll
    for (int k = 0; k < 4; ++k) {
        int t = threadIdx.x + k * K3_THREADS;
        if (t < NPLANES) g_counts[t] = 0u;            // reset for next replay
    }
    if (threadIdx.x == 0) {
        int mk = skey[0];
        #pragma unroll
        for (int w = 1; w < 8; ++w) mk = max(mk, skey[w]);
        int best = 1023 - (mk & 0xFFF);
        float4 bp = g_planes[best];
        g_acc.bestPlane = bp;
        float a = bp.x, b = bp.y, c = bp.z, d = bp.w;
        float n2 = a * a + b * b + c * c;
        float cos_t = c / sqrtf(n2);
        float sin_t = sqrtf((a * a + b * b) / n2);
        float sab = sqrtf(a * a + b * b);
        float u1 = b / sab;
        float u2 = -a / sab;
        g_acc.dz = d / c;
        g_acc.R20 = -u2 * sin_t;
        g_acc.R21 = u1 * sin_t;
        g_acc.R22 = cos_t;
        g_tick3 = 0u;
    }
}

// ----------------------------- kernel 5 ------------------------------------
// Inlier z stats, 4 px/thread (float4), 225 blocks; tail: finalize + reset.
__global__ __launch_bounds__(256)
void k5_stats(float* __restrict__ out, int out_size) {
    int i4 = blockIdx.x * 256 + threadIdx.x;
    float invg = 1.0f / __int_as_float(g_acc.gmaxBits);
    float th = g_acc.thresh;
    float4 bp = g_acc.bestPlane;
    float R20 = g_acc.R20, R21 = g_acc.R21, R22 = g_acc.R22, dz = g_acc.dz;
    const float INF = __int_as_float(0x7f800000);

    float4 vx = ((const float4*)g_cx)[i4];
    float4 vy = ((const float4*)g_cy)[i4];
    float4 vz = ((const float4*)g_cz)[i4];
    float pxv[4] = { vx.x, vx.y, vx.z, vx.w };
    float pyv[4] = { vy.x, vy.y, vy.z, vy.w };
    float pzv[4] = { vz.x, vz.y, vz.z, vz.w };

    float zmx = -INF, zmn = INF, sZc = 0.f;
    int ic = 0;
    #pragma unroll
    for (int j = 0; j < 4; ++j) {
        float px = pxv[j] * invg, py = pyv[j] * invg, pz = pzv[j] * invg;
        float d = plane_dist(bp, px, py, pz);
        bool in = (fabsf(d) <= th);
        float zc = __fmaf_rn(pz + dz, R22, __fmaf_rn(py, R21, px * R20));
        if (in) {
            zmx = fmaxf(zmx, zc);
            zmn = fminf(zmn, zc);
            sZc += zc;
            ic++;
        }
    }

    zmx = wred_max_f(zmx);
    zmn = wred_min_f(zmn);
    sZc = wred_add_f(sZc);
    ic = wred_add_i(ic);

    __shared__ float rs[8][4];
    int wid = threadIdx.x >> 5;
    if ((threadIdx.x & 31) == 0) {
        rs[wid][0] = zmx; rs[wid][1] = zmn; rs[wid][2] = sZc; rs[wid][3] = (float)ic;
    }
    __syncthreads();
    if (threadIdx.x == 0) {
        float tmx = -INF, tmn = INF, tS = 0.f, tC = 0.f;
        #pragma unroll
        for (int w = 0; w < 8; ++w) {
            tmx = fmaxf(tmx, rs[w][0]); tmn = fminf(tmn, rs[w][1]);
            tS += rs[w][2]; tC += rs[w][3];
        }
        atomicMax(&g_acc.zmaxEnc, encf(tmx));
        atomicMin(&g_acc.zminEnc, encf(tmn));
        atomicAdd(&g_acc.sumZc, (double)tS);
        atomicAdd(&g_acc.icnt, (unsigned long long)(int)tC);
    }

    // ---- last-block tail (of 225): finalize + reset for next replay ----
    __shared__ unsigned s_last;
    __syncthreads();
    if (threadIdx.x == 0) {
        __threadfence();
        s_last = atomicAdd(&g_tick5, 1u);
    }
    __syncthreads();
    if (s_last != PIX4_BLOCKS - 1) return;

    if (threadIdx.x == 0) {
        __threadfence();
        unsigned long long cm = __ldcg(&g_acc.cntM); if (cm < 1) cm = 1;
        double cnt = (double)cm;
        float lX = (float)sqrt(__ldcg(&g_acc.sumX) / cnt);
        float lY = (float)sqrt(__ldcg(&g_acc.sumY) / cnt);
        float lZ = (float)sqrt(__ldcg(&g_acc.sumZ) / cnt);
        float rmse_log = (float)(10000.0 * sqrt(__ldcg(&g_acc.sumLog) / cnt));
        float loss17 = rmse_log * fabsf(10.0f * (3.0f - expf(lX) - expf(lY) - expf(lZ)));

        unsigned long long icu = __ldcg(&g_acc.icnt); if (icu < 1) icu = 1;
        double icnt = (double)icu;
        double meanZc = __ldcg(&g_acc.sumZc) / icnt;
        float zmax = decf(__ldcg(&g_acc.zmaxEnc));
        float zmin = decf(__ldcg(&g_acc.zminEnc));
        float below = (float)((double)zmax - meanZc);
        float above = (float)(meanZc - (double)zmin);
        if (above == 0.0f) above = 1e-7f;
        float pmdg = 1000.0f * (above + below);
        float loss_curv = loss17 + pmdg;

        float vals[7] = { rmse_log, lX, lY, lZ, pmdg, loss17, loss_curv };
        for (int j = 0; j < 7 && j < out_size; ++j) out[j] = vals[j];

        // reset accumulators for next graph replay
        g_acc.sumX = 0.0; g_acc.sumY = 0.0; g_acc.sumZ = 0.0; g_acc.sumLog = 0.0;
        g_acc.cntM = 0ull;
        g_acc.gmaxBits = 0;
        g_acc.zmaxEnc = ENC_NEG_INF;
        g_acc.zminEnc = ENC_POS_INF;
        g_acc.icnt = 0ull;
        g_acc.sumZc = 0.0;
        g_tick5 = 0u;
    }
}

// ----------------------------- launch -------------------------------------
extern "C" void kernel_launch(void* const* d_in, const int* in_sizes, int n_in,
                              void* d_out, int out_size) {
    const float4* fake4 = (const float4*)d_in[0];
    const float4* real4 = (const float4*)d_in[1];
    const int* epoch = (const int*)d_in[2];
    (void)in_sizes; (void)n_in;

    k1_stats<<<PIX4_BLOCKS, 256>>>(fake4, real4);
    k2_planes<<<4, 256>>>(epoch);
    dim3 g3(K3_XBLOCKS, K3_YBLOCKS);
    k3_count<<<g3, K3_THREADS>>>();
    k5_stats<<<PIX4_BLOCKS, 256>>>((float*)d_out, out_size);
}